// round 4
// baseline (speedup 1.0000x reference)
#include <cuda_runtime.h>
#include <cstdint>

#define Bn 8
#define Nn 2048
#define Fn 512

// ---------------------------------------------------------------------------
// Scratch (__device__ globals; no allocation allowed)
// ---------------------------------------------------------------------------
__device__ float g_hidden[Bn * Nn * Fn];   // tf32-rounded hidden, 33.5 MB
__device__ float g_Wr[Fn * Fn];            // tf32-rounded W
__device__ float g_s[Bn * Nn];
__device__ float g_d[Bn * Nn];

// ---------------------------------------------------------------------------
// Helpers
// ---------------------------------------------------------------------------
__device__ __forceinline__ uint32_t smem_u32(const void* p) {
    uint32_t a;
    asm("{ .reg .u64 t; cvta.to.shared.u64 t, %1; cvt.u32.u64 %0, t; }"
        : "=r"(a) : "l"(p));
    return a;
}
__device__ __forceinline__ uint32_t f2tf32(float v) {
    uint32_t r;
    asm("cvt.rna.tf32.f32 %0, %1;" : "=r"(r) : "f"(v));
    return r;
}
__device__ __forceinline__ void cp16(uint32_t dst, const void* src) {
    asm volatile("cp.async.cg.shared.global [%0], [%1], 16;"
                 :: "r"(dst), "l"(src));
}
#define CP_COMMIT() asm volatile("cp.async.commit_group;" ::: "memory")
#define CP_WAIT0()  asm volatile("cp.async.wait_group 0;" ::: "memory")

__device__ __forceinline__ void mma8(float* c, uint32_t a0, uint32_t a1,
                                     uint32_t a2, uint32_t a3,
                                     uint32_t b0, uint32_t b1) {
    asm volatile("mma.sync.aligned.m16n8k8.row.col.f32.tf32.tf32.f32 "
        "{%0,%1,%2,%3},{%4,%5,%6,%7},{%8,%9},{%0,%1,%2,%3};"
        : "+f"(c[0]), "+f"(c[1]), "+f"(c[2]), "+f"(c[3])
        : "r"(a0), "r"(a1), "r"(a2), "r"(a3), "r"(b0), "r"(b1));
}

// Fast exp via exp2 polynomial on FMA pipe (rel err ~2e-6).
__device__ __forceinline__ float exp_fast(float x) {
    float y = x * 1.4426950408889634f;
    y = fmaxf(y, -125.0f);
    float z = y + 12582912.0f;
    int   ei = __float_as_int(z) - 0x4B400000;
    float f = y - (z - 12582912.0f);
    float p = 1.3333558146e-3f;
    p = fmaf(p, f, 9.6181291076e-3f);
    p = fmaf(p, f, 5.5504108664e-2f);
    p = fmaf(p, f, 2.4022650695e-1f);
    p = fmaf(p, f, 6.9314718056e-1f);
    p = fmaf(p, f, 1.0f);
    return p * __int_as_float((ei + 127) << 23);
}

// ---------------------------------------------------------------------------
// kW: round W to tf32 once (so kA can cp.async it raw)
// ---------------------------------------------------------------------------
__global__ __launch_bounds__(256)
void kW(const float* __restrict__ W) {
    int i = blockIdx.x * 256 + threadIdx.x;
    float4 v = ((const float4*)W)[i];
    float4 o;
    o.x = __uint_as_float(f2tf32(v.x));
    o.y = __uint_as_float(f2tf32(v.y));
    o.z = __uint_as_float(f2tf32(v.z));
    o.w = __uint_as_float(f2tf32(v.w));
    ((float4*)g_Wr)[i] = o;
}

// ---------------------------------------------------------------------------
// kA: hidden = text @ W + b (tf32 mma.sync). Block 128x128, 8 warps (2m x 4n),
// warp tile 64x32, K-tile 32. Stores tf32-rounded hidden (fp32 container).
// smem: A 2*128*36*4 = 36864 ; B 2*32*136*4 = 34816 ; total 71680
// ---------------------------------------------------------------------------
#define SA 36
#define SBA 136

__global__ __launch_bounds__(256, 2)
void kA(const float* __restrict__ text, const float* __restrict__ bias) {
    extern __shared__ unsigned char smraw[];
    uint32_t* Ast = (uint32_t*)smraw;
    uint32_t* Bst = (uint32_t*)(smraw + 36864);
    const uint32_t sb = smem_u32(smraw);

    const int tid = threadIdx.x;
    const int w = tid >> 5, lane = tid & 31;
    const int g = lane >> 2, tg = lane & 3;
    const int wm = w >> 2, wn = w & 3;
    const int row0 = blockIdx.x * 128;
    const int f0 = blockIdx.y * 128;

    float acc[4][4][4];
    #pragma unroll
    for (int mf = 0; mf < 4; mf++)
        #pragma unroll
        for (int nf = 0; nf < 4; nf++)
            #pragma unroll
            for (int q = 0; q < 4; q++) acc[mf][nf][q] = 0.0f;

    float4 pf[4];

    {
        const float* src = text + (size_t)row0 * Fn;
        #pragma unroll
        for (int q = 0; q < 4; q++) {
            int idx = tid + 256 * q, r = idx >> 3, c4 = idx & 7;
            pf[q] = *(const float4*)(src + (size_t)r * Fn + c4 * 4);
        }
        const float* wsrc = g_Wr + f0;
        #pragma unroll
        for (int q = 0; q < 4; q++) {
            int idx = tid + 256 * q, k = idx >> 5, nc = idx & 31;
            cp16(sb + 36864u + (uint32_t)(k * SBA + nc * 4) * 4,
                 wsrc + (size_t)k * Fn + nc * 4);
        }
        CP_COMMIT();
    }

    #pragma unroll 1
    for (int c = 0; c < 16; c++) {
        const int buf = c & 1;
        CP_WAIT0();
        __syncthreads();

        {
            uint32_t* A = Ast + buf * 128 * SA;
            #pragma unroll
            for (int q = 0; q < 4; q++) {
                int idx = tid + 256 * q, r = idx >> 3, c4 = idx & 7;
                A[r * SA + c4 * 4 + 0] = f2tf32(pf[q].x);
                A[r * SA + c4 * 4 + 1] = f2tf32(pf[q].y);
                A[r * SA + c4 * 4 + 2] = f2tf32(pf[q].z);
                A[r * SA + c4 * 4 + 3] = f2tf32(pf[q].w);
            }
        }
        if (c < 15) {
            const int nb = (c + 1) & 1;
            const float* wsrc = g_Wr + (size_t)((c + 1) * 32) * Fn + f0;
            #pragma unroll
            for (int q = 0; q < 4; q++) {
                int idx = tid + 256 * q, k = idx >> 5, nc = idx & 31;
                cp16(sb + 36864u + (uint32_t)(nb * 32 * SBA + k * SBA + nc * 4) * 4,
                     wsrc + (size_t)k * Fn + nc * 4);
            }
            CP_COMMIT();
            const float* src = text + (size_t)row0 * Fn + (c + 1) * 32;
            #pragma unroll
            for (int q = 0; q < 4; q++) {
                int idx = tid + 256 * q, r = idx >> 3, c4 = idx & 7;
                pf[q] = *(const float4*)(src + (size_t)r * Fn + c4 * 4);
            }
        }
        __syncthreads();

        {
            const uint32_t* A = Ast + buf * 128 * SA;
            const uint32_t* B = Bst + buf * 32 * SBA;
            #pragma unroll
            for (int ks = 0; ks < 4; ks++) {
                const int kb = ks * 8;
                uint32_t bf[4][2];
                #pragma unroll
                for (int nf = 0; nf < 4; nf++) {
                    int nb2 = wn * 32 + nf * 8 + g;
                    bf[nf][0] = B[(kb + tg) * SBA + nb2];
                    bf[nf][1] = B[(kb + 4 + tg) * SBA + nb2];
                }
                #pragma unroll
                for (int mf = 0; mf < 4; mf++) {
                    int rb = wm * 64 + mf * 16;
                    uint32_t a0 = A[(rb + g) * SA + kb + tg];
                    uint32_t a1 = A[(rb + g + 8) * SA + kb + tg];
                    uint32_t a2 = A[(rb + g) * SA + kb + tg + 4];
                    uint32_t a3 = A[(rb + g + 8) * SA + kb + tg + 4];
                    #pragma unroll
                    for (int nf = 0; nf < 4; nf++)
                        mma8(acc[mf][nf], a0, a1, a2, a3, bf[nf][0], bf[nf][1]);
                }
            }
        }
    }

    #pragma unroll
    for (int mf = 0; mf < 4; mf++) {
        int r0 = row0 + wm * 64 + mf * 16 + g;
        #pragma unroll
        for (int nf = 0; nf < 4; nf++) {
            int f = f0 + wn * 32 + nf * 8 + 2 * tg;
            float b0v = __ldg(bias + f), b1v = __ldg(bias + f + 1);
            float2 v0, v1;
            v0.x = __uint_as_float(f2tf32(acc[mf][nf][0] + b0v));
            v0.y = __uint_as_float(f2tf32(acc[mf][nf][1] + b1v));
            v1.x = __uint_as_float(f2tf32(acc[mf][nf][2] + b0v));
            v1.y = __uint_as_float(f2tf32(acc[mf][nf][3] + b1v));
            *(float2*)&g_hidden[(size_t)r0 * Fn + f] = v0;
            *(float2*)&g_hidden[(size_t)(r0 + 8) * Fn + f] = v1;
        }
    }
}

// ---------------------------------------------------------------------------
// kSD: s = hidden.a_src, d = hidden.a_dst per node
// ---------------------------------------------------------------------------
__global__ __launch_bounds__(128)
void kSD(const float* __restrict__ a_src, const float* __restrict__ a_dst) {
    const int row = blockIdx.x;
    const int tid = threadIdx.x;
    const float* h = g_hidden + (size_t)row * Fn;
    float ss = 0.0f, dd = 0.0f;
    for (int f = tid; f < Fn; f += 128) {
        float v = h[f];
        ss = fmaf(v, a_src[f], ss);
        dd = fmaf(v, a_dst[f], dd);
    }
    #pragma unroll
    for (int off = 16; off > 0; off >>= 1) {
        ss += __shfl_down_sync(0xffffffffu, ss, off);
        dd += __shfl_down_sync(0xffffffffu, dd, off);
    }
    __shared__ float rs[4], rd[4];
    if ((tid & 31) == 0) { rs[tid >> 5] = ss; rd[tid >> 5] = dd; }
    __syncthreads();
    if (tid == 0) {
        g_s[row] = rs[0] + rs[1] + rs[2] + rs[3];
        g_d[row] = rd[0] + rd[1] + rd[2] + rd[3];
    }
}

// ---------------------------------------------------------------------------
// kB: fused mask + leakyReLU + exp + PV GEMM.
// Block 128 rows x 128 feats, 8 warps (2m x 4n), warp tile 64x32,
// K(j)-tile 32, 64 ktiles. 2 CTAs/SM (regs<=128, smem 111KB).
// smem layout (bytes):
//   Ps 0..36864 | Bs 36864..71680 | Aj 71680..104448 |
//   s_s 104448 | s_l 104960 | s_d 105472..113664
// ---------------------------------------------------------------------------
#define SBB 136
#define PS_OFF  0u
#define BS_OFF  36864u
#define AJ_OFF  71680u
#define SS_OFF  104448u
#define SL_OFF  104960u
#define SD_OFF  105472u
#define KB_SMEM 113664

__global__ __launch_bounds__(256, 2)
void kB(const int* __restrict__ adj, float* __restrict__ out) {
    extern __shared__ unsigned char smraw[];
    uint32_t* Ps  = (uint32_t*)(smraw + PS_OFF);
    uint32_t* Bst = (uint32_t*)(smraw + BS_OFF);
    int*      Aj  = (int*)     (smraw + AJ_OFF);
    float*    s_s = (float*)   (smraw + SS_OFF);
    float*    s_l = (float*)   (smraw + SL_OFF);
    float*    s_d = (float*)   (smraw + SD_OFF);
    const uint32_t sb = smem_u32(smraw);

    const int tid = threadIdx.x;
    const int w = tid >> 5, lane = tid & 31;
    const int g = lane >> 2, tg = lane & 3;
    const int wm = w & 1, wn = w >> 1;
    const int i0 = blockIdx.x * 128;
    const int f0 = blockIdx.y * 128;
    const int b = blockIdx.z;
    const size_t rowg = (size_t)b * Nn + i0;

    if (tid < 128) s_s[tid] = g_s[rowg + tid];
    for (int i = tid; i < Nn; i += 256) s_d[i] = g_d[b * Nn + i];

    float acc[4][4][4];
    #pragma unroll
    for (int mf = 0; mf < 4; mf++)
        #pragma unroll
        for (int nf = 0; nf < 4; nf++)
            #pragma unroll
            for (int q = 0; q < 4; q++) acc[mf][nf][q] = 0.0f;

    float lpart[16];
    #pragma unroll
    for (int p = 0; p < 16; p++) lpart[p] = 0.0f;

    // group 0: B tile (hidden 32x128) + adj tile (128x32)
    {
        const float* hsrc = g_hidden + ((size_t)b * Nn) * Fn + f0;
        #pragma unroll
        for (int q = 0; q < 4; q++) {
            int idx = tid + 256 * q, k = idx >> 5, nc = idx & 31;
            cp16(sb + BS_OFF + (uint32_t)(k * SBB + nc * 4) * 4,
                 hsrc + (size_t)k * Fn + nc * 4);
        }
        const int* asrc = adj + rowg * Nn;
        #pragma unroll
        for (int q = 0; q < 4; q++) {
            int idx = tid + 256 * q, r = idx >> 3, c4 = idx & 7;
            cp16(sb + AJ_OFF + (uint32_t)(r * 32 + c4 * 4) * 4,
                 asrc + (size_t)r * Nn + c4 * 4);
        }
        CP_COMMIT();
    }

    #pragma unroll 1
    for (int c = 0; c < 64; c++) {
        const int buf = c & 1;
        CP_WAIT0();
        __syncthreads();

        if (c < 63) {
            const int nb = (c + 1) & 1;
            const float* hsrc = g_hidden + ((size_t)(b * Nn + (c + 1) * 32)) * Fn + f0;
            #pragma unroll
            for (int q = 0; q < 4; q++) {
                int idx = tid + 256 * q, k = idx >> 5, nc = idx & 31;
                cp16(sb + BS_OFF + (uint32_t)(nb * 32 * SBB + k * SBB + nc * 4) * 4,
                     hsrc + (size_t)k * Fn + nc * 4);
            }
            const int* asrc = adj + rowg * Nn + (c + 1) * 32;
            #pragma unroll
            for (int q = 0; q < 4; q++) {
                int idx = tid + 256 * q, r = idx >> 3, c4 = idx & 7;
                cp16(sb + AJ_OFF + (uint32_t)(nb * 4096 + r * 32 + c4 * 4) * 4,
                     asrc + (size_t)r * Nn + c4 * 4);
            }
            CP_COMMIT();
        }

        // build P tile from staged adj
        {
            const int* aj = Aj + buf * 4096;
            uint32_t* P = Ps + buf * 128 * SA;
            const float dj = s_d[c * 32 + lane];
            #pragma unroll
            for (int p = 0; p < 16; p++) {
                int r = 8 * p + w;
                int m = aj[r * 32 + lane];
                float sc = s_s[r] + dj;
                sc = (sc >= 0.0f) ? sc : 0.2f * sc;
                if (m) sc = -10000.0f;
                uint32_t tv = f2tf32(exp_fast(sc));
                lpart[p] += __uint_as_float(tv);
                P[r * SA + lane] = tv;
            }
        }
        __syncthreads();

        // MMA on buffer buf
        {
            const uint32_t* A = Ps + buf * 128 * SA;
            const uint32_t* B = Bst + buf * 32 * SBB;
            #pragma unroll
            for (int ks = 0; ks < 4; ks++) {
                const int kb = ks * 8;
                uint32_t bf[4][2];
                #pragma unroll
                for (int nf = 0; nf < 4; nf++) {
                    int nb2 = wn * 32 + nf * 8 + g;
                    bf[nf][0] = B[(kb + tg) * SBB + nb2];
                    bf[nf][1] = B[(kb + 4 + tg) * SBB + nb2];
                }
                #pragma unroll
                for (int mf = 0; mf < 4; mf++) {
                    int rb = wm * 64 + mf * 16;
                    uint32_t a0 = A[(rb + g) * SA + kb + tg];
                    uint32_t a1 = A[(rb + g + 8) * SA + kb + tg];
                    uint32_t a2 = A[(rb + g) * SA + kb + tg + 4];
                    uint32_t a3 = A[(rb + g + 8) * SA + kb + tg + 4];
                    #pragma unroll
                    for (int nf = 0; nf < 4; nf++)
                        mma8(acc[mf][nf], a0, a1, a2, a3, bf[nf][0], bf[nf][1]);
                }
            }
        }
        __syncthreads();
    }

    // reduce row sums -> s_l, invert
    #pragma unroll
    for (int p = 0; p < 16; p++) {
        float v = lpart[p];
        #pragma unroll
        for (int off = 16; off > 0; off >>= 1)
            v += __shfl_xor_sync(0xffffffffu, v, off);
        if (lane == 0) s_l[8 * p + w] = v;
    }
    __syncthreads();
    if (tid < 128) s_l[tid] = 1.0f / s_l[tid];
    __syncthreads();

    // epilogue: scale by 1/l, store
    #pragma unroll
    for (int mf = 0; mf < 4; mf++) {
        int rl = wm * 64 + mf * 16 + g;
        float i0v = s_l[rl], i1v = s_l[rl + 8];
        size_t o0 = (rowg + rl) * Fn;
        size_t o1 = (rowg + rl + 8) * Fn;
        #pragma unroll
        for (int nf = 0; nf < 4; nf++) {
            int f = f0 + wn * 32 + nf * 8 + 2 * tg;
            float2 v0, v1;
            v0.x = acc[mf][nf][0] * i0v;
            v0.y = acc[mf][nf][1] * i0v;
            v1.x = acc[mf][nf][2] * i1v;
            v1.y = acc[mf][nf][3] * i1v;
            *(float2*)&out[o0 + f] = v0;
            *(float2*)&out[o1 + f] = v1;
        }
    }
}

// ---------------------------------------------------------------------------
extern "C" void kernel_launch(void* const* d_in, const int* in_sizes, int n_in,
                              void* d_out, int out_size) {
    const float* text  = (const float*)d_in[0];
    const int*   adj   = (const int*)  d_in[1];
    const float* W     = (const float*)d_in[2];
    const float* bias  = (const float*)d_in[3];
    const float* a_src = (const float*)d_in[4];
    const float* a_dst = (const float*)d_in[5];
    float* out = (float*)d_out;

    cudaFuncSetAttribute(kA, cudaFuncAttributeMaxDynamicSharedMemorySize, 71680);
    cudaFuncSetAttribute(kB, cudaFuncAttributeMaxDynamicSharedMemorySize, KB_SMEM);

    kW<<<256, 256>>>(W);
    kA<<<dim3(128, 4), 256, 71680>>>(text, bias);
    kSD<<<Bn * Nn, 128>>>(a_src, a_dst);
    kB<<<dim3(16, 4, 8), 256, KB_SMEM>>>(adj, out);
}

// round 5
// speedup vs baseline: 1.2284x; 1.2284x over previous
#include <cuda_runtime.h>
#include <cuda_fp16.h>
#include <cstdint>

#define Bn 8
#define Nn 2048
#define Fn 512

// ---------------------------------------------------------------------------
// Scratch (__device__ globals; no allocation allowed)
// ---------------------------------------------------------------------------
__device__ __half g_hT[Bn * Fn * Nn];   // hidden^T [b][f][j], half (16.8 MB)
__device__ __half g_Wh[Fn * Fn];        // W^T [f_out][f_in], half
__device__ float  g_s[Bn * Nn];
__device__ float  g_d[Bn * Nn];

// ---------------------------------------------------------------------------
// Helpers
// ---------------------------------------------------------------------------
__device__ __forceinline__ uint32_t smem_u32(const void* p) {
    uint32_t a;
    asm("{ .reg .u64 t; cvta.to.shared.u64 t, %1; cvt.u32.u64 %0, t; }"
        : "=r"(a) : "l"(p));
    return a;
}
__device__ __forceinline__ void cp16(uint32_t dst, const void* src) {
    asm volatile("cp.async.cg.shared.global [%0], [%1], 16;"
                 :: "r"(dst), "l"(src));
}
#define CP_COMMIT() asm volatile("cp.async.commit_group;" ::: "memory")
#define CP_WAIT0()  asm volatile("cp.async.wait_group 0;" ::: "memory")

// fp16 m16n8k16, fp32 accumulate
__device__ __forceinline__ void mma16(float* c, uint32_t a0, uint32_t a1,
                                      uint32_t a2, uint32_t a3,
                                      uint32_t b0, uint32_t b1) {
    asm volatile("mma.sync.aligned.m16n8k16.row.col.f32.f16.f16.f32 "
        "{%0,%1,%2,%3},{%4,%5,%6,%7},{%8,%9},{%0,%1,%2,%3};"
        : "+f"(c[0]), "+f"(c[1]), "+f"(c[2]), "+f"(c[3])
        : "r"(a0), "r"(a1), "r"(a2), "r"(a3), "r"(b0), "r"(b1));
}

// exp(x) * 2^-4 via exp2 polynomial on FMA pipe. Scale cancels in P/sum(P),
// gives fp16 16x overflow headroom. Clamp keeps exponent field valid.
__device__ __forceinline__ float exp_fast_s(float x) {
    float y = x * 1.4426950408889634f;
    y = fmaxf(y, -100.0f);
    float z = y + 12582912.0f;
    int   ei = __float_as_int(z) - 0x4B400000;
    float f = y - (z - 12582912.0f);
    float p = 1.3333558146e-3f;
    p = fmaf(p, f, 9.6181291076e-3f);
    p = fmaf(p, f, 5.5504108664e-2f);
    p = fmaf(p, f, 2.4022650695e-1f);
    p = fmaf(p, f, 6.9314718056e-1f);
    p = fmaf(p, f, 1.0f);
    return p * __int_as_float((ei + 123) << 23);   // 2^(ei-4)
}

// ---------------------------------------------------------------------------
// kW: g_Wh[n][k] = half(W[k][n])  (transpose + convert)
// ---------------------------------------------------------------------------
__global__ __launch_bounds__(256)
void kW(const float* __restrict__ W) {
    __shared__ float t[32][33];
    int tx = threadIdx.x & 31, ty = threadIdx.x >> 5;
    int bx = blockIdx.x, by = blockIdx.y;
    #pragma unroll
    for (int q = 0; q < 4; q++)
        t[ty + 8 * q][tx] = W[(by * 32 + ty + 8 * q) * Fn + bx * 32 + tx];
    __syncthreads();
    #pragma unroll
    for (int q = 0; q < 4; q++)
        g_Wh[(bx * 32 + ty + 8 * q) * Fn + by * 32 + tx] =
            __float2half_rn(t[tx][ty + 8 * q]);
}

// ---------------------------------------------------------------------------
// kA: hidden = text @ W + b (fp16 mma m16n8k16). Block 128 rows x 128 f,
// 8 warps (2m x 4n), warp tile 64x32, K-tile 32 (2 ksteps).
// Writes hidden transposed: g_hT[b][f][j], half.
// smem: A 2*128*40*2 = 20480 ; B 2*128*40*2 = 20480 ; total 40960
// A tile: [row][k] 40-half stride; B tile: [n][k] 40-half stride.
// ---------------------------------------------------------------------------
#define SP 40

__global__ __launch_bounds__(256, 2)
void kA(const float* __restrict__ text, const float* __restrict__ bias) {
    extern __shared__ unsigned char smraw[];
    __half* Ah = (__half*)smraw;
    __half* Bh = (__half*)(smraw + 20480);
    const uint32_t sb = smem_u32(smraw);

    const int tid = threadIdx.x;
    const int w = tid >> 5, lane = tid & 31;
    const int g = lane >> 2, tg = lane & 3;
    const int wm = w >> 2, wn = w & 3;
    const int row0 = blockIdx.x * 128;
    const int f0 = blockIdx.y * 128;
    const int bb = row0 >> 11;
    const int jl0 = row0 & (Nn - 1);

    float acc[4][4][4];
    #pragma unroll
    for (int mf = 0; mf < 4; mf++)
        #pragma unroll
        for (int nf = 0; nf < 4; nf++)
            #pragma unroll
            for (int q = 0; q < 4; q++) acc[mf][nf][q] = 0.0f;

    float4 pf[4];

    // prefetch A(0) regs; issue B(0) cp.async
    {
        const float* src = text + (size_t)row0 * Fn;
        #pragma unroll
        for (int q = 0; q < 4; q++) {
            int idx = tid + 256 * q, r = idx >> 3, c4 = idx & 7;
            pf[q] = *(const float4*)(src + (size_t)r * Fn + c4 * 4);
        }
        const __half* wsrc = g_Wh + f0 * Fn;
        #pragma unroll
        for (int q = 0; q < 2; q++) {
            int idx = tid + 256 * q, n = idx >> 2, ch = idx & 3;
            cp16(sb + 20480u + (uint32_t)(n * SP + ch * 8) * 2,
                 wsrc + (size_t)n * Fn + ch * 8);
        }
        CP_COMMIT();
    }

    #pragma unroll 1
    for (int c = 0; c < 16; c++) {
        const int buf = c & 1;
        CP_WAIT0();
        __syncthreads();

        // store A(c) regs -> smem halves
        {
            __half* A = Ah + buf * 128 * SP;
            #pragma unroll
            for (int q = 0; q < 4; q++) {
                int idx = tid + 256 * q, r = idx >> 3, c4 = idx & 7;
                __half* dst = A + r * SP + c4 * 4;
                *(__half2*)(dst)     = __floats2half2_rn(pf[q].x, pf[q].y);
                *(__half2*)(dst + 2) = __floats2half2_rn(pf[q].z, pf[q].w);
            }
        }
        if (c < 15) {
            const int nb = (c + 1) & 1;
            const __half* wsrc = g_Wh + (size_t)f0 * Fn + (c + 1) * 32;
            #pragma unroll
            for (int q = 0; q < 2; q++) {
                int idx = tid + 256 * q, n = idx >> 2, ch = idx & 3;
                cp16(sb + 20480u + (uint32_t)(nb * 128 * SP + n * SP + ch * 8) * 2,
                     wsrc + (size_t)n * Fn + ch * 8);
            }
            CP_COMMIT();
            const float* src = text + (size_t)row0 * Fn + (c + 1) * 32;
            #pragma unroll
            for (int q = 0; q < 4; q++) {
                int idx = tid + 256 * q, r = idx >> 3, c4 = idx & 7;
                pf[q] = *(const float4*)(src + (size_t)r * Fn + c4 * 4);
            }
        }
        __syncthreads();

        // MMA on buffer buf
        {
            const __half* A = Ah + buf * 128 * SP;
            const __half* B = Bh + buf * 128 * SP;
            #pragma unroll
            for (int ks = 0; ks < 2; ks++) {
                uint32_t bf[4][2];
                #pragma unroll
                for (int nf = 0; nf < 4; nf++) {
                    const __half* bp = B + (wn * 32 + nf * 8 + g) * SP + 16 * ks + 2 * tg;
                    bf[nf][0] = *(const uint32_t*)(bp);
                    bf[nf][1] = *(const uint32_t*)(bp + 8);
                }
                #pragma unroll
                for (int mf = 0; mf < 4; mf++) {
                    int rb = wm * 64 + mf * 16;
                    const __half* ap0 = A + (rb + g) * SP + 16 * ks + 2 * tg;
                    const __half* ap1 = A + (rb + g + 8) * SP + 16 * ks + 2 * tg;
                    uint32_t a0 = *(const uint32_t*)(ap0);
                    uint32_t a1 = *(const uint32_t*)(ap1);
                    uint32_t a2 = *(const uint32_t*)(ap0 + 8);
                    uint32_t a3 = *(const uint32_t*)(ap1 + 8);
                    #pragma unroll
                    for (int nf = 0; nf < 4; nf++)
                        mma16(acc[mf][nf], a0, a1, a2, a3, bf[nf][0], bf[nf][1]);
                }
            }
        }
    }

    // epilogue: + bias, write transposed half hT[b][f][j]
    __half* hb = g_hT + (size_t)bb * Fn * Nn;
    #pragma unroll
    for (int mf = 0; mf < 4; mf++) {
        int jl = jl0 + wm * 64 + mf * 16 + g;
        #pragma unroll
        for (int nf = 0; nf < 4; nf++) {
            int f = f0 + wn * 32 + nf * 8 + 2 * tg;
            float b0v = __ldg(bias + f), b1v = __ldg(bias + f + 1);
            hb[(size_t)f * Nn + jl]           = __float2half_rn(acc[mf][nf][0] + b0v);
            hb[(size_t)(f + 1) * Nn + jl]     = __float2half_rn(acc[mf][nf][1] + b1v);
            hb[(size_t)f * Nn + jl + 8]       = __float2half_rn(acc[mf][nf][2] + b0v);
            hb[(size_t)(f + 1) * Nn + jl + 8] = __float2half_rn(acc[mf][nf][3] + b1v);
        }
    }
}

// ---------------------------------------------------------------------------
// kSD: s[j] = sum_f hT[f][j]*a_src[f], d likewise. Coalesced along j.
// grid (Nn/256, Bn), 256 threads.
// ---------------------------------------------------------------------------
__global__ __launch_bounds__(256)
void kSD(const float* __restrict__ a_src, const float* __restrict__ a_dst) {
    __shared__ float sa[Fn], sd[Fn];
    const int tid = threadIdx.x;
    const int j = blockIdx.x * 256 + tid;
    const int b = blockIdx.y;
    for (int i = tid; i < Fn; i += 256) { sa[i] = a_src[i]; sd[i] = a_dst[i]; }
    __syncthreads();
    const __half* h = g_hT + (size_t)b * Fn * Nn + j;
    float ss = 0.0f, dd = 0.0f;
    #pragma unroll 8
    for (int f = 0; f < Fn; f++) {
        float v = __half2float(h[(size_t)f * Nn]);
        ss = fmaf(v, sa[f], ss);
        dd = fmaf(v, sd[f], dd);
    }
    g_s[b * Nn + j] = ss;
    g_d[b * Nn + j] = dd;
}

// ---------------------------------------------------------------------------
// kB: fused mask + leakyReLU + exp + PV GEMM (fp16 m16n8k16).
// Block 128 rows x 128 f, 8 warps (2m x 4n), warp tile 64x32, K(j)-tile 32.
// smem bytes: P 0..20480 | B 20480..40960 | Aj 40960..73728 |
//             s_s 73728 | s_l 74240 | s_d 74752..82944
// ---------------------------------------------------------------------------
#define PS_OFF  0u
#define BS_OFF  20480u
#define AJ_OFF  40960u
#define SS_OFF  73728u
#define SL_OFF  74240u
#define SD_OFF  74752u
#define KB_SMEM 82944

__global__ __launch_bounds__(256, 2)
void kB(const int* __restrict__ adj, float* __restrict__ out) {
    extern __shared__ unsigned char smraw[];
    __half*  Ph  = (__half*)(smraw + PS_OFF);
    __half*  Bh  = (__half*)(smraw + BS_OFF);
    int*     Aj  = (int*)   (smraw + AJ_OFF);
    float*   s_s = (float*) (smraw + SS_OFF);
    float*   s_l = (float*) (smraw + SL_OFF);
    float*   s_d = (float*) (smraw + SD_OFF);
    const uint32_t sb = smem_u32(smraw);

    const int tid = threadIdx.x;
    const int w = tid >> 5, lane = tid & 31;
    const int g = lane >> 2, tg = lane & 3;
    const int wm = w & 1, wn = w >> 1;
    const int i0 = blockIdx.x * 128;
    const int f0 = blockIdx.y * 128;
    const int b = blockIdx.z;
    const size_t rowg = (size_t)b * Nn + i0;

    if (tid < 128) s_s[tid] = g_s[rowg + tid];
    for (int i = tid; i < Nn; i += 256) s_d[i] = g_d[b * Nn + i];

    float acc[4][4][4];
    #pragma unroll
    for (int mf = 0; mf < 4; mf++)
        #pragma unroll
        for (int nf = 0; nf < 4; nf++)
            #pragma unroll
            for (int q = 0; q < 4; q++) acc[mf][nf][q] = 0.0f;

    float lpart[16];
    #pragma unroll
    for (int p = 0; p < 16; p++) lpart[p] = 0.0f;

    const __half* hsrc0 = g_hT + (size_t)b * Fn * Nn + (size_t)f0 * Nn;

    // group 0: B tile (hT 128f x 32j) + adj tile (128 x 32)
    {
        #pragma unroll
        for (int q = 0; q < 2; q++) {
            int idx = tid + 256 * q, n = idx >> 2, ch = idx & 3;
            cp16(sb + BS_OFF + (uint32_t)(n * SP + ch * 8) * 2,
                 hsrc0 + (size_t)n * Nn + ch * 8);
        }
        const int* asrc = adj + rowg * Nn;
        #pragma unroll
        for (int q = 0; q < 4; q++) {
            int idx = tid + 256 * q, r = idx >> 3, c4 = idx & 7;
            cp16(sb + AJ_OFF + (uint32_t)(r * 32 + c4 * 4) * 4,
                 asrc + (size_t)r * Nn + c4 * 4);
        }
        CP_COMMIT();
    }

    #pragma unroll 1
    for (int c = 0; c < 64; c++) {
        const int buf = c & 1;
        CP_WAIT0();
        __syncthreads();

        if (c < 63) {
            const int nb = (c + 1) & 1;
            const __half* hsrc = hsrc0 + (c + 1) * 32;
            #pragma unroll
            for (int q = 0; q < 2; q++) {
                int idx = tid + 256 * q, n = idx >> 2, ch = idx & 3;
                cp16(sb + BS_OFF + (uint32_t)(nb * 128 * SP + n * SP + ch * 8) * 2,
                     hsrc + (size_t)n * Nn + ch * 8);
            }
            const int* asrc = adj + rowg * Nn + (c + 1) * 32;
            #pragma unroll
            for (int q = 0; q < 4; q++) {
                int idx = tid + 256 * q, r = idx >> 3, c4 = idx & 7;
                cp16(sb + AJ_OFF + (uint32_t)(nb * 4096 + r * 32 + c4 * 4) * 4,
                     asrc + (size_t)r * Nn + c4 * 4);
            }
            CP_COMMIT();
        }

        // build P tile (half) from staged adj
        {
            const int* aj = Aj + buf * 4096;
            __half* P = Ph + buf * 128 * SP;
            const float dj = s_d[c * 32 + lane];
            #pragma unroll
            for (int p = 0; p < 16; p++) {
                int r = 8 * p + w;
                int m = aj[r * 32 + lane];
                float sc = s_s[r] + dj;
                sc = (sc >= 0.0f) ? sc : 0.2f * sc;
                if (m) sc = -10000.0f;
                float e = exp_fast_s(sc);
                lpart[p] += e;
                P[r * SP + lane] = __float2half_rn(e);
            }
        }
        __syncthreads();

        // MMA on buffer buf
        {
            const __half* A = Ph + buf * 128 * SP;
            const __half* B = Bh + buf * 128 * SP;
            #pragma unroll
            for (int ks = 0; ks < 2; ks++) {
                uint32_t bf[4][2];
                #pragma unroll
                for (int nf = 0; nf < 4; nf++) {
                    const __half* bp = B + (wn * 32 + nf * 8 + g) * SP + 16 * ks + 2 * tg;
                    bf[nf][0] = *(const uint32_t*)(bp);
                    bf[nf][1] = *(const uint32_t*)(bp + 8);
                }
                #pragma unroll
                for (int mf = 0; mf < 4; mf++) {
                    int rb = wm * 64 + mf * 16;
                    const __half* ap0 = A + (rb + g) * SP + 16 * ks + 2 * tg;
                    const __half* ap1 = A + (rb + g + 8) * SP + 16 * ks + 2 * tg;
                    uint32_t a0 = *(const uint32_t*)(ap0);
                    uint32_t a1 = *(const uint32_t*)(ap1);
                    uint32_t a2 = *(const uint32_t*)(ap0 + 8);
                    uint32_t a3 = *(const uint32_t*)(ap1 + 8);
                    #pragma unroll
                    for (int nf = 0; nf < 4; nf++)
                        mma16(acc[mf][nf], a0, a1, a2, a3, bf[nf][0], bf[nf][1]);
                }
            }
        }
        __syncthreads();
    }

    // reduce row sums -> s_l, invert
    #pragma unroll
    for (int p = 0; p < 16; p++) {
        float v = lpart[p];
        #pragma unroll
        for (int off = 16; off > 0; off >>= 1)
            v += __shfl_xor_sync(0xffffffffu, v, off);
        if (lane == 0) s_l[8 * p + w] = v;
    }
    __syncthreads();
    if (tid < 128) s_l[tid] = 1.0f / s_l[tid];
    __syncthreads();

    // epilogue: scale by 1/l, store fp32
    #pragma unroll
    for (int mf = 0; mf < 4; mf++) {
        int rl = wm * 64 + mf * 16 + g;
        float i0v = s_l[rl], i1v = s_l[rl + 8];
        size_t o0 = (rowg + rl) * Fn;
        size_t o1 = (rowg + rl + 8) * Fn;
        #pragma unroll
        for (int nf = 0; nf < 4; nf++) {
            int f = f0 + wn * 32 + nf * 8 + 2 * tg;
            float2 v0, v1;
            v0.x = acc[mf][nf][0] * i0v;
            v0.y = acc[mf][nf][1] * i0v;
            v1.x = acc[mf][nf][2] * i1v;
            v1.y = acc[mf][nf][3] * i1v;
            *(float2*)&out[o0 + f] = v0;
            *(float2*)&out[o1 + f] = v1;
        }
    }
}

// ---------------------------------------------------------------------------
extern "C" void kernel_launch(void* const* d_in, const int* in_sizes, int n_in,
                              void* d_out, int out_size) {
    const float* text  = (const float*)d_in[0];
    const int*   adj   = (const int*)  d_in[1];
    const float* W     = (const float*)d_in[2];
    const float* bias  = (const float*)d_in[3];
    const float* a_src = (const float*)d_in[4];
    const float* a_dst = (const float*)d_in[5];
    float* out = (float*)d_out;

    cudaFuncSetAttribute(kA, cudaFuncAttributeMaxDynamicSharedMemorySize, 40960);
    cudaFuncSetAttribute(kB, cudaFuncAttributeMaxDynamicSharedMemorySize, KB_SMEM);

    kW<<<dim3(16, 16), 256>>>(W);
    kA<<<dim3(128, 4), 256, 40960>>>(text, bias);
    kSD<<<dim3(Nn / 256, Bn), 256>>>(a_src, a_dst);
    kB<<<dim3(16, 4, 8), 256, KB_SMEM>>>(adj, out);
}

// round 6
// speedup vs baseline: 1.4335x; 1.1670x over previous
#include <cuda_runtime.h>
#include <cuda_fp16.h>
#include <cstdint>

#define Bn 8
#define Nn 2048
#define Fn 512

// ---------------------------------------------------------------------------
// Scratch (__device__ globals; no allocation allowed)
// ---------------------------------------------------------------------------
__device__ __half g_hT[Bn * Fn * Nn];   // hidden^T [b][f][j], half (16.8 MB)
__device__ __half g_P[(size_t)Bn * Nn * Nn];  // P (scaled exp), half (67 MB)
__device__ __half g_Wh[Fn * Fn];        // W^T [f_out][f_in], half
__device__ float  g_s[Bn * Nn];
__device__ float  g_d[Bn * Nn];
__device__ float  g_linv[Bn * Nn];

// ---------------------------------------------------------------------------
// Helpers
// ---------------------------------------------------------------------------
__device__ __forceinline__ uint32_t smem_u32(const void* p) {
    uint32_t a;
    asm("{ .reg .u64 t; cvta.to.shared.u64 t, %1; cvt.u32.u64 %0, t; }"
        : "=r"(a) : "l"(p));
    return a;
}
__device__ __forceinline__ void cp16(uint32_t dst, const void* src) {
    asm volatile("cp.async.cg.shared.global [%0], [%1], 16;"
                 :: "r"(dst), "l"(src));
}
#define CP_COMMIT() asm volatile("cp.async.commit_group;" ::: "memory")
#define CP_WAIT0()  asm volatile("cp.async.wait_group 0;" ::: "memory")

// fp16 m16n8k16, fp32 accumulate
__device__ __forceinline__ void mma16(float* c, uint32_t a0, uint32_t a1,
                                      uint32_t a2, uint32_t a3,
                                      uint32_t b0, uint32_t b1) {
    asm volatile("mma.sync.aligned.m16n8k16.row.col.f32.f16.f16.f32 "
        "{%0,%1,%2,%3},{%4,%5,%6,%7},{%8,%9},{%0,%1,%2,%3};"
        : "+f"(c[0]), "+f"(c[1]), "+f"(c[2]), "+f"(c[3])
        : "r"(a0), "r"(a1), "r"(a2), "r"(a3), "r"(b0), "r"(b1));
}

// exp(x) * 2^-4 via exp2 polynomial on FMA pipe. Scale cancels in P/sum(P),
// gives fp16 16x overflow headroom. Clamp keeps exponent field valid.
__device__ __forceinline__ float exp_fast_s(float x) {
    float y = x * 1.4426950408889634f;
    y = fmaxf(y, -100.0f);
    float z = y + 12582912.0f;
    int   ei = __float_as_int(z) - 0x4B400000;
    float f = y - (z - 12582912.0f);
    float p = 1.3333558146e-3f;
    p = fmaf(p, f, 9.6181291076e-3f);
    p = fmaf(p, f, 5.5504108664e-2f);
    p = fmaf(p, f, 2.4022650695e-1f);
    p = fmaf(p, f, 6.9314718056e-1f);
    p = fmaf(p, f, 1.0f);
    return p * __int_as_float((ei + 123) << 23);   // 2^(ei-4)
}

// ---------------------------------------------------------------------------
// kW: g_Wh[n][k] = half(W[k][n])  (transpose + convert)
// ---------------------------------------------------------------------------
__global__ __launch_bounds__(256)
void kW(const float* __restrict__ W) {
    __shared__ float t[32][33];
    int tx = threadIdx.x & 31, ty = threadIdx.x >> 5;
    int bx = blockIdx.x, by = blockIdx.y;
    #pragma unroll
    for (int q = 0; q < 4; q++)
        t[ty + 8 * q][tx] = W[(by * 32 + ty + 8 * q) * Fn + bx * 32 + tx];
    __syncthreads();
    #pragma unroll
    for (int q = 0; q < 4; q++)
        g_Wh[(bx * 32 + ty + 8 * q) * Fn + by * 32 + tx] =
            __float2half_rn(t[tx][ty + 8 * q]);
}

// ---------------------------------------------------------------------------
// kA: hidden = text @ W + b (fp16 mma m16n8k16). Block 128 rows x 128 f,
// 8 warps (2m x 4n), warp tile 64x32, K-tile 32 (2 ksteps).
// Writes hidden transposed: g_hT[b][f][j], half.
// ---------------------------------------------------------------------------
#define SP 40

__global__ __launch_bounds__(256, 2)
void kA(const float* __restrict__ text, const float* __restrict__ bias) {
    extern __shared__ unsigned char smraw[];
    __half* Ah = (__half*)smraw;
    __half* Bh = (__half*)(smraw + 20480);
    const uint32_t sb = smem_u32(smraw);

    const int tid = threadIdx.x;
    const int w = tid >> 5, lane = tid & 31;
    const int g = lane >> 2, tg = lane & 3;
    const int wm = w >> 2, wn = w & 3;
    const int row0 = blockIdx.x * 128;
    const int f0 = blockIdx.y * 128;
    const int bb = row0 >> 11;
    const int jl0 = row0 & (Nn - 1);

    float acc[4][4][4];
    #pragma unroll
    for (int mf = 0; mf < 4; mf++)
        #pragma unroll
        for (int nf = 0; nf < 4; nf++)
            #pragma unroll
            for (int q = 0; q < 4; q++) acc[mf][nf][q] = 0.0f;

    float4 pf[4];

    {
        const float* src = text + (size_t)row0 * Fn;
        #pragma unroll
        for (int q = 0; q < 4; q++) {
            int idx = tid + 256 * q, r = idx >> 3, c4 = idx & 7;
            pf[q] = *(const float4*)(src + (size_t)r * Fn + c4 * 4);
        }
        const __half* wsrc = g_Wh + f0 * Fn;
        #pragma unroll
        for (int q = 0; q < 2; q++) {
            int idx = tid + 256 * q, n = idx >> 2, ch = idx & 3;
            cp16(sb + 20480u + (uint32_t)(n * SP + ch * 8) * 2,
                 wsrc + (size_t)n * Fn + ch * 8);
        }
        CP_COMMIT();
    }

    #pragma unroll 1
    for (int c = 0; c < 16; c++) {
        const int buf = c & 1;
        CP_WAIT0();
        __syncthreads();

        {
            __half* A = Ah + buf * 128 * SP;
            #pragma unroll
            for (int q = 0; q < 4; q++) {
                int idx = tid + 256 * q, r = idx >> 3, c4 = idx & 7;
                __half* dst = A + r * SP + c4 * 4;
                *(__half2*)(dst)     = __floats2half2_rn(pf[q].x, pf[q].y);
                *(__half2*)(dst + 2) = __floats2half2_rn(pf[q].z, pf[q].w);
            }
        }
        if (c < 15) {
            const int nb = (c + 1) & 1;
            const __half* wsrc = g_Wh + (size_t)f0 * Fn + (c + 1) * 32;
            #pragma unroll
            for (int q = 0; q < 2; q++) {
                int idx = tid + 256 * q, n = idx >> 2, ch = idx & 3;
                cp16(sb + 20480u + (uint32_t)(nb * 128 * SP + n * SP + ch * 8) * 2,
                     wsrc + (size_t)n * Fn + ch * 8);
            }
            CP_COMMIT();
            const float* src = text + (size_t)row0 * Fn + (c + 1) * 32;
            #pragma unroll
            for (int q = 0; q < 4; q++) {
                int idx = tid + 256 * q, r = idx >> 3, c4 = idx & 7;
                pf[q] = *(const float4*)(src + (size_t)r * Fn + c4 * 4);
            }
        }
        __syncthreads();

        {
            const __half* A = Ah + buf * 128 * SP;
            const __half* B = Bh + buf * 128 * SP;
            #pragma unroll
            for (int ks = 0; ks < 2; ks++) {
                uint32_t bf[4][2];
                #pragma unroll
                for (int nf = 0; nf < 4; nf++) {
                    const __half* bp = B + (wn * 32 + nf * 8 + g) * SP + 16 * ks + 2 * tg;
                    bf[nf][0] = *(const uint32_t*)(bp);
                    bf[nf][1] = *(const uint32_t*)(bp + 8);
                }
                #pragma unroll
                for (int mf = 0; mf < 4; mf++) {
                    int rb = wm * 64 + mf * 16;
                    const __half* ap0 = A + (rb + g) * SP + 16 * ks + 2 * tg;
                    const __half* ap1 = A + (rb + g + 8) * SP + 16 * ks + 2 * tg;
                    uint32_t a0 = *(const uint32_t*)(ap0);
                    uint32_t a1 = *(const uint32_t*)(ap1);
                    uint32_t a2 = *(const uint32_t*)(ap0 + 8);
                    uint32_t a3 = *(const uint32_t*)(ap1 + 8);
                    #pragma unroll
                    for (int nf = 0; nf < 4; nf++)
                        mma16(acc[mf][nf], a0, a1, a2, a3, bf[nf][0], bf[nf][1]);
                }
            }
        }
    }

    __half* hb = g_hT + (size_t)bb * Fn * Nn;
    #pragma unroll
    for (int mf = 0; mf < 4; mf++) {
        int jl = jl0 + wm * 64 + mf * 16 + g;
        #pragma unroll
        for (int nf = 0; nf < 4; nf++) {
            int f = f0 + wn * 32 + nf * 8 + 2 * tg;
            float b0v = __ldg(bias + f), b1v = __ldg(bias + f + 1);
            hb[(size_t)f * Nn + jl]           = __float2half_rn(acc[mf][nf][0] + b0v);
            hb[(size_t)(f + 1) * Nn + jl]     = __float2half_rn(acc[mf][nf][1] + b1v);
            hb[(size_t)f * Nn + jl + 8]       = __float2half_rn(acc[mf][nf][2] + b0v);
            hb[(size_t)(f + 1) * Nn + jl + 8] = __float2half_rn(acc[mf][nf][3] + b1v);
        }
    }
}

// ---------------------------------------------------------------------------
// kSD: s[j] = sum_f hT[f][j]*a_src[f], d likewise. Coalesced along j.
// ---------------------------------------------------------------------------
__global__ __launch_bounds__(256)
void kSD(const float* __restrict__ a_src, const float* __restrict__ a_dst) {
    __shared__ float sa[Fn], sd[Fn];
    const int tid = threadIdx.x;
    const int j = blockIdx.x * 256 + tid;
    const int b = blockIdx.y;
    for (int i = tid; i < Fn; i += 256) { sa[i] = a_src[i]; sd[i] = a_dst[i]; }
    __syncthreads();
    const __half* h = g_hT + (size_t)b * Fn * Nn + j;
    float ss = 0.0f, dd = 0.0f;
    #pragma unroll 8
    for (int f = 0; f < Fn; f++) {
        float v = __half2float(h[(size_t)f * Nn]);
        ss = fmaf(v, sa[f], ss);
        dd = fmaf(v, sd[f], dd);
    }
    g_s[b * Nn + j] = ss;
    g_d[b * Nn + j] = dd;
}

// ---------------------------------------------------------------------------
// kP: P[b][i][j] = 2^-4 * exp(masked lrelu(s_i + d_j)), g_linv = 1/rowsum.
// grid (Nn/64, Bn), 256 threads. Warp w handles rows w*8..w*8+7;
// lane processes 4 consecutive j (int4 adj loads, half2 stores).
// ---------------------------------------------------------------------------
__global__ __launch_bounds__(256)
void kP(const int* __restrict__ adj) {
    __shared__ float s_d[Nn];
    const int tid = threadIdx.x, w = tid >> 5, lane = tid & 31;
    const int i0 = blockIdx.x * 64;
    const int b = blockIdx.y;
    const size_t rowg = (size_t)b * Nn + i0;
    for (int i = tid; i < Nn; i += 256) s_d[i] = g_d[b * Nn + i];
    __syncthreads();

    #pragma unroll 1
    for (int rr = 0; rr < 8; rr++) {
        const int r = w * 8 + rr;
        const float si = g_s[rowg + r];
        const int4* arow = (const int4*)(adj + (rowg + r) * Nn);
        __half2* prow = (__half2*)(g_P + (rowg + r) * Nn);
        const float4* dsrc = (const float4*)s_d;
        float lsum = 0.0f;
        #pragma unroll 4
        for (int q = lane; q < Nn / 4; q += 32) {
            int4 m = arow[q];
            float4 dv = dsrc[q];
            float sc0 = si + dv.x, sc1 = si + dv.y;
            float sc2 = si + dv.z, sc3 = si + dv.w;
            sc0 = (sc0 >= 0.0f) ? sc0 : 0.2f * sc0;
            sc1 = (sc1 >= 0.0f) ? sc1 : 0.2f * sc1;
            sc2 = (sc2 >= 0.0f) ? sc2 : 0.2f * sc2;
            sc3 = (sc3 >= 0.0f) ? sc3 : 0.2f * sc3;
            if (m.x) sc0 = -10000.0f;
            if (m.y) sc1 = -10000.0f;
            if (m.z) sc2 = -10000.0f;
            if (m.w) sc3 = -10000.0f;
            float e0 = exp_fast_s(sc0), e1 = exp_fast_s(sc1);
            float e2 = exp_fast_s(sc2), e3 = exp_fast_s(sc3);
            lsum += (e0 + e1) + (e2 + e3);
            prow[2 * q]     = __floats2half2_rn(e0, e1);
            prow[2 * q + 1] = __floats2half2_rn(e2, e3);
        }
        #pragma unroll
        for (int off = 16; off > 0; off >>= 1)
            lsum += __shfl_xor_sync(0xffffffffu, lsum, off);
        if (lane == 0) g_linv[rowg + r] = 1.0f / lsum;
    }
}

// ---------------------------------------------------------------------------
// kB: pure fp16 GEMM  out = (P @ hT^T) * linv.
// Block 128 rows x 128 f, 8 warps (2m x 4n), warp tile 64x32, K(j)-tile 32.
// smem: A(P) 2*128*40*2 = 20480 | B(hT) 20480 | s_l 512   total 41472
// ---------------------------------------------------------------------------
#define KB_SMEM 41472

__global__ __launch_bounds__(256, 2)
void kB(float* __restrict__ out) {
    extern __shared__ unsigned char smraw[];
    __half* Ah  = (__half*)smraw;
    __half* Bh  = (__half*)(smraw + 20480);
    float*  s_l = (float*)(smraw + 40960);
    const uint32_t sb = smem_u32(smraw);

    const int tid = threadIdx.x;
    const int w = tid >> 5, lane = tid & 31;
    const int g = lane >> 2, tg = lane & 3;
    const int wm = w & 1, wn = w >> 1;
    const int i0 = blockIdx.x * 128;
    const int f0 = blockIdx.y * 128;
    const int b = blockIdx.z;
    const size_t rowg = (size_t)b * Nn + i0;

    if (tid < 128) s_l[tid] = g_linv[rowg + tid];

    float acc[4][4][4];
    #pragma unroll
    for (int mf = 0; mf < 4; mf++)
        #pragma unroll
        for (int nf = 0; nf < 4; nf++)
            #pragma unroll
            for (int q = 0; q < 4; q++) acc[mf][nf][q] = 0.0f;

    const __half* psrc0 = g_P + rowg * Nn;
    const __half* hsrc0 = g_hT + (size_t)b * Fn * Nn + (size_t)f0 * Nn;

    // group 0
    {
        #pragma unroll
        for (int q = 0; q < 2; q++) {
            int idx = tid + 256 * q, r = idx >> 2, ch = idx & 3;
            cp16(sb + (uint32_t)(r * SP + ch * 8) * 2,
                 psrc0 + (size_t)r * Nn + ch * 8);
        }
        #pragma unroll
        for (int q = 0; q < 2; q++) {
            int idx = tid + 256 * q, n = idx >> 2, ch = idx & 3;
            cp16(sb + 20480u + (uint32_t)(n * SP + ch * 8) * 2,
                 hsrc0 + (size_t)n * Nn + ch * 8);
        }
        CP_COMMIT();
    }

    #pragma unroll 1
    for (int c = 0; c < 64; c++) {
        const int buf = c & 1;
        CP_WAIT0();
        __syncthreads();

        if (c < 63) {
            const int nb = (c + 1) & 1;
            const __half* psrc = psrc0 + (c + 1) * 32;
            #pragma unroll
            for (int q = 0; q < 2; q++) {
                int idx = tid + 256 * q, r = idx >> 2, ch = idx & 3;
                cp16(sb + (uint32_t)(nb * 128 * SP + r * SP + ch * 8) * 2,
                     psrc + (size_t)r * Nn + ch * 8);
            }
            const __half* hsrc = hsrc0 + (c + 1) * 32;
            #pragma unroll
            for (int q = 0; q < 2; q++) {
                int idx = tid + 256 * q, n = idx >> 2, ch = idx & 3;
                cp16(sb + 20480u + (uint32_t)(nb * 128 * SP + n * SP + ch * 8) * 2,
                     hsrc + (size_t)n * Nn + ch * 8);
            }
            CP_COMMIT();
        }

        // MMA on buffer buf
        {
            const __half* A = Ah + buf * 128 * SP;
            const __half* B = Bh + buf * 128 * SP;
            #pragma unroll
            for (int ks = 0; ks < 2; ks++) {
                uint32_t bf[4][2];
                #pragma unroll
                for (int nf = 0; nf < 4; nf++) {
                    const __half* bp = B + (wn * 32 + nf * 8 + g) * SP + 16 * ks + 2 * tg;
                    bf[nf][0] = *(const uint32_t*)(bp);
                    bf[nf][1] = *(const uint32_t*)(bp + 8);
                }
                #pragma unroll
                for (int mf = 0; mf < 4; mf++) {
                    int rb = wm * 64 + mf * 16;
                    const __half* ap0 = A + (rb + g) * SP + 16 * ks + 2 * tg;
                    const __half* ap1 = A + (rb + g + 8) * SP + 16 * ks + 2 * tg;
                    uint32_t a0 = *(const uint32_t*)(ap0);
                    uint32_t a1 = *(const uint32_t*)(ap1);
                    uint32_t a2 = *(const uint32_t*)(ap0 + 8);
                    uint32_t a3 = *(const uint32_t*)(ap1 + 8);
                    #pragma unroll
                    for (int nf = 0; nf < 4; nf++)
                        mma16(acc[mf][nf], a0, a1, a2, a3, bf[nf][0], bf[nf][1]);
                }
            }
        }
        __syncthreads();
    }

    // epilogue: scale by 1/l, store fp32
    #pragma unroll
    for (int mf = 0; mf < 4; mf++) {
        int rl = wm * 64 + mf * 16 + g;
        float i0v = s_l[rl], i1v = s_l[rl + 8];
        size_t o0 = (rowg + rl) * Fn;
        size_t o1 = (rowg + rl + 8) * Fn;
        #pragma unroll
        for (int nf = 0; nf < 4; nf++) {
            int f = f0 + wn * 32 + nf * 8 + 2 * tg;
            float2 v0, v1;
            v0.x = acc[mf][nf][0] * i0v;
            v0.y = acc[mf][nf][1] * i0v;
            v1.x = acc[mf][nf][2] * i1v;
            v1.y = acc[mf][nf][3] * i1v;
            *(float2*)&out[o0 + f] = v0;
            *(float2*)&out[o1 + f] = v1;
        }
    }
}

// ---------------------------------------------------------------------------
extern "C" void kernel_launch(void* const* d_in, const int* in_sizes, int n_in,
                              void* d_out, int out_size) {
    const float* text  = (const float*)d_in[0];
    const int*   adj   = (const int*)  d_in[1];
    const float* W     = (const float*)d_in[2];
    const float* bias  = (const float*)d_in[3];
    const float* a_src = (const float*)d_in[4];
    const float* a_dst = (const float*)d_in[5];
    float* out = (float*)d_out;

    cudaFuncSetAttribute(kA, cudaFuncAttributeMaxDynamicSharedMemorySize, 40960);
    cudaFuncSetAttribute(kB, cudaFuncAttributeMaxDynamicSharedMemorySize, KB_SMEM);

    kW<<<dim3(16, 16), 256>>>(W);
    kA<<<dim3(128, 4), 256, 40960>>>(text, bias);
    kSD<<<dim3(Nn / 256, Bn), 256>>>(a_src, a_dst);
    kP<<<dim3(Nn / 64, Bn), 256>>>(adj);
    kB<<<dim3(16, 4, 8), 256, KB_SMEM>>>(out);
}

// round 7
// speedup vs baseline: 1.7835x; 1.2442x over previous
#include <cuda_runtime.h>
#include <cuda_fp16.h>
#include <cstdint>

#define Bn 8
#define Nn 2048
#define Fn 512

// ---------------------------------------------------------------------------
// Scratch (__device__ globals; no allocation allowed)
// ---------------------------------------------------------------------------
__device__ __half g_hT[Bn * Fn * Nn];         // hidden^T [b][f][j], half (16.8 MB)
__device__ __half g_P[(size_t)Bn * Nn * Nn];  // P (scaled exp), half (67 MB)
__device__ __half g_Wh[Fn * Fn];              // W^T [f_out][f_in], half
__device__ float  g_s[Bn * Nn];
__device__ float  g_d[Bn * Nn];
__device__ float  g_sp[4][Bn * Nn];           // f-chunk partials
__device__ float  g_dp[4][Bn * Nn];
__device__ float  g_linv[Bn * Nn];

// ---------------------------------------------------------------------------
// Helpers
// ---------------------------------------------------------------------------
__device__ __forceinline__ uint32_t smem_u32(const void* p) {
    uint32_t a;
    asm("{ .reg .u64 t; cvta.to.shared.u64 t, %1; cvt.u32.u64 %0, t; }"
        : "=r"(a) : "l"(p));
    return a;
}
__device__ __forceinline__ void cp16(uint32_t dst, const void* src) {
    asm volatile("cp.async.cg.shared.global [%0], [%1], 16;"
                 :: "r"(dst), "l"(src));
}
#define CP_COMMIT() asm volatile("cp.async.commit_group;" ::: "memory")
#define CP_WAIT0()  asm volatile("cp.async.wait_group 0;" ::: "memory")

// fp16 m16n8k16, fp32 accumulate
__device__ __forceinline__ void mma16(float* c, uint32_t a0, uint32_t a1,
                                      uint32_t a2, uint32_t a3,
                                      uint32_t b0, uint32_t b1) {
    asm volatile("mma.sync.aligned.m16n8k16.row.col.f32.f16.f16.f32 "
        "{%0,%1,%2,%3},{%4,%5,%6,%7},{%8,%9},{%0,%1,%2,%3};"
        : "+f"(c[0]), "+f"(c[1]), "+f"(c[2]), "+f"(c[3])
        : "r"(a0), "r"(a1), "r"(a2), "r"(a3), "r"(b0), "r"(b1));
}

// exp(x) * 2^-4 via exp2 polynomial on FMA pipe. Scale cancels in P/sum(P),
// gives fp16 16x overflow headroom. Clamp keeps exponent field valid.
__device__ __forceinline__ float exp_fast_s(float x) {
    float y = x * 1.4426950408889634f;
    y = fmaxf(y, -100.0f);
    float z = y + 12582912.0f;
    int   ei = __float_as_int(z) - 0x4B400000;
    float f = y - (z - 12582912.0f);
    float p = 1.3333558146e-3f;
    p = fmaf(p, f, 9.6181291076e-3f);
    p = fmaf(p, f, 5.5504108664e-2f);
    p = fmaf(p, f, 2.4022650695e-1f);
    p = fmaf(p, f, 6.9314718056e-1f);
    p = fmaf(p, f, 1.0f);
    return p * __int_as_float((ei + 123) << 23);   // 2^(ei-4)
}

// ---------------------------------------------------------------------------
// kW: g_Wh[n][k] = half(W[k][n])  (transpose + convert)
// ---------------------------------------------------------------------------
__global__ __launch_bounds__(256)
void kW(const float* __restrict__ W) {
    __shared__ float t[32][33];
    int tx = threadIdx.x & 31, ty = threadIdx.x >> 5;
    int bx = blockIdx.x, by = blockIdx.y;
    #pragma unroll
    for (int q = 0; q < 4; q++)
        t[ty + 8 * q][tx] = W[(by * 32 + ty + 8 * q) * Fn + bx * 32 + tx];
    __syncthreads();
    #pragma unroll
    for (int q = 0; q < 4; q++)
        g_Wh[(bx * 32 + ty + 8 * q) * Fn + by * 32 + tx] =
            __float2half_rn(t[tx][ty + 8 * q]);
}

// ---------------------------------------------------------------------------
// kA: hidden = text @ W + b (fp16 mma m16n8k16). Block 128 rows x 128 f,
// 8 warps (2m x 4n), warp tile 64x32, K-tile 32 (2 ksteps).
// Writes hidden transposed: g_hT[b][f][j], half.
// ---------------------------------------------------------------------------
#define SP 40

__global__ __launch_bounds__(256, 2)
void kA(const float* __restrict__ text, const float* __restrict__ bias) {
    extern __shared__ unsigned char smraw[];
    __half* Ah = (__half*)smraw;
    __half* Bh = (__half*)(smraw + 20480);
    const uint32_t sb = smem_u32(smraw);

    const int tid = threadIdx.x;
    const int w = tid >> 5, lane = tid & 31;
    const int g = lane >> 2, tg = lane & 3;
    const int wm = w >> 2, wn = w & 3;
    const int row0 = blockIdx.x * 128;
    const int f0 = blockIdx.y * 128;
    const int bb = row0 >> 11;
    const int jl0 = row0 & (Nn - 1);

    float acc[4][4][4];
    #pragma unroll
    for (int mf = 0; mf < 4; mf++)
        #pragma unroll
        for (int nf = 0; nf < 4; nf++)
            #pragma unroll
            for (int q = 0; q < 4; q++) acc[mf][nf][q] = 0.0f;

    float4 pf[4];

    {
        const float* src = text + (size_t)row0 * Fn;
        #pragma unroll
        for (int q = 0; q < 4; q++) {
            int idx = tid + 256 * q, r = idx >> 3, c4 = idx & 7;
            pf[q] = *(const float4*)(src + (size_t)r * Fn + c4 * 4);
        }
        const __half* wsrc = g_Wh + f0 * Fn;
        #pragma unroll
        for (int q = 0; q < 2; q++) {
            int idx = tid + 256 * q, n = idx >> 2, ch = idx & 3;
            cp16(sb + 20480u + (uint32_t)(n * SP + ch * 8) * 2,
                 wsrc + (size_t)n * Fn + ch * 8);
        }
        CP_COMMIT();
    }

    #pragma unroll 1
    for (int c = 0; c < 16; c++) {
        const int buf = c & 1;
        CP_WAIT0();
        __syncthreads();

        {
            __half* A = Ah + buf * 128 * SP;
            #pragma unroll
            for (int q = 0; q < 4; q++) {
                int idx = tid + 256 * q, r = idx >> 3, c4 = idx & 7;
                __half* dst = A + r * SP + c4 * 4;
                *(__half2*)(dst)     = __floats2half2_rn(pf[q].x, pf[q].y);
                *(__half2*)(dst + 2) = __floats2half2_rn(pf[q].z, pf[q].w);
            }
        }
        if (c < 15) {
            const int nb = (c + 1) & 1;
            const __half* wsrc = g_Wh + (size_t)f0 * Fn + (c + 1) * 32;
            #pragma unroll
            for (int q = 0; q < 2; q++) {
                int idx = tid + 256 * q, n = idx >> 2, ch = idx & 3;
                cp16(sb + 20480u + (uint32_t)(nb * 128 * SP + n * SP + ch * 8) * 2,
                     wsrc + (size_t)n * Fn + ch * 8);
            }
            CP_COMMIT();
            const float* src = text + (size_t)row0 * Fn + (c + 1) * 32;
            #pragma unroll
            for (int q = 0; q < 4; q++) {
                int idx = tid + 256 * q, r = idx >> 3, c4 = idx & 7;
                pf[q] = *(const float4*)(src + (size_t)r * Fn + c4 * 4);
            }
        }
        __syncthreads();

        {
            const __half* A = Ah + buf * 128 * SP;
            const __half* B = Bh + buf * 128 * SP;
            #pragma unroll
            for (int ks = 0; ks < 2; ks++) {
                uint32_t bf[4][2];
                #pragma unroll
                for (int nf = 0; nf < 4; nf++) {
                    const __half* bp = B + (wn * 32 + nf * 8 + g) * SP + 16 * ks + 2 * tg;
                    bf[nf][0] = *(const uint32_t*)(bp);
                    bf[nf][1] = *(const uint32_t*)(bp + 8);
                }
                #pragma unroll
                for (int mf = 0; mf < 4; mf++) {
                    int rb = wm * 64 + mf * 16;
                    const __half* ap0 = A + (rb + g) * SP + 16 * ks + 2 * tg;
                    const __half* ap1 = A + (rb + g + 8) * SP + 16 * ks + 2 * tg;
                    uint32_t a0 = *(const uint32_t*)(ap0);
                    uint32_t a1 = *(const uint32_t*)(ap1);
                    uint32_t a2 = *(const uint32_t*)(ap0 + 8);
                    uint32_t a3 = *(const uint32_t*)(ap1 + 8);
                    #pragma unroll
                    for (int nf = 0; nf < 4; nf++)
                        mma16(acc[mf][nf], a0, a1, a2, a3, bf[nf][0], bf[nf][1]);
                }
            }
        }
    }

    __half* hb = g_hT + (size_t)bb * Fn * Nn;
    #pragma unroll
    for (int mf = 0; mf < 4; mf++) {
        int jl = jl0 + wm * 64 + mf * 16 + g;
        #pragma unroll
        for (int nf = 0; nf < 4; nf++) {
            int f = f0 + wn * 32 + nf * 8 + 2 * tg;
            float b0v = __ldg(bias + f), b1v = __ldg(bias + f + 1);
            hb[(size_t)f * Nn + jl]           = __float2half_rn(acc[mf][nf][0] + b0v);
            hb[(size_t)(f + 1) * Nn + jl]     = __float2half_rn(acc[mf][nf][1] + b1v);
            hb[(size_t)f * Nn + jl + 8]       = __float2half_rn(acc[mf][nf][2] + b0v);
            hb[(size_t)(f + 1) * Nn + jl + 8] = __float2half_rn(acc[mf][nf][3] + b1v);
        }
    }
}

// ---------------------------------------------------------------------------
// kSD stage 1: partial dot products over a 128-f chunk.
// grid (Nn/256, Bn, 4), 256 threads. Coalesced along j.
// ---------------------------------------------------------------------------
__global__ __launch_bounds__(256)
void kSD(const float* __restrict__ a_src, const float* __restrict__ a_dst) {
    __shared__ float sa[128], sd[128];
    const int tid = threadIdx.x;
    const int j = blockIdx.x * 256 + tid;
    const int b = blockIdx.y;
    const int fc = blockIdx.z;
    if (tid < 128) { sa[tid] = a_src[fc * 128 + tid]; sd[tid] = a_dst[fc * 128 + tid]; }
    __syncthreads();
    const __half* h = g_hT + (size_t)b * Fn * Nn + (size_t)fc * 128 * Nn + j;
    float ss = 0.0f, dd = 0.0f;
    #pragma unroll 16
    for (int f = 0; f < 128; f++) {
        float v = __half2float(h[(size_t)f * Nn]);
        ss = fmaf(v, sa[f], ss);
        dd = fmaf(v, sd[f], dd);
    }
    g_sp[fc][b * Nn + j] = ss;
    g_dp[fc][b * Nn + j] = dd;
}

// ---------------------------------------------------------------------------
// kSD stage 2: reduce 4 partials. grid 64, 256 threads.
// ---------------------------------------------------------------------------
__global__ __launch_bounds__(256)
void kSDr() {
    const int i = blockIdx.x * 256 + threadIdx.x;
    g_s[i] = (g_sp[0][i] + g_sp[1][i]) + (g_sp[2][i] + g_sp[3][i]);
    g_d[i] = (g_dp[0][i] + g_dp[1][i]) + (g_dp[2][i] + g_dp[3][i]);
}

// ---------------------------------------------------------------------------
// kP: P[b][i][j] = 2^-4 * exp(masked lrelu(s_i + d_j)), g_linv = 1/rowsum.
// Warp-per-row: grid (Nn/8, Bn) = 2048 CTAs, 8 warps each.
// Lane handles 16 fully-unrolled j-quads (int4 adj / float4 d loads).
// ---------------------------------------------------------------------------
__global__ __launch_bounds__(256)
void kP(const int* __restrict__ adj) {
    const int tid = threadIdx.x, w = tid >> 5, lane = tid & 31;
    const int b = blockIdx.y;
    const int r = blockIdx.x * 8 + w;
    const size_t rowg = (size_t)b * Nn + r;
    const float si = g_s[rowg];
    const int4*   arow = (const int4*)(adj + rowg * Nn);
    const float4* dsrc = (const float4*)(g_d + (size_t)b * Nn);
    __half2* prow = (__half2*)(g_P + rowg * Nn);

    float lsum = 0.0f;
    #pragma unroll
    for (int q0 = 0; q0 < 16; q0++) {
        const int q = q0 * 32 + lane;
        int4 m = __ldg(arow + q);
        float4 dv = __ldg(dsrc + q);
        float sc0 = si + dv.x, sc1 = si + dv.y;
        float sc2 = si + dv.z, sc3 = si + dv.w;
        sc0 = (sc0 >= 0.0f) ? sc0 : 0.2f * sc0;
        sc1 = (sc1 >= 0.0f) ? sc1 : 0.2f * sc1;
        sc2 = (sc2 >= 0.0f) ? sc2 : 0.2f * sc2;
        sc3 = (sc3 >= 0.0f) ? sc3 : 0.2f * sc3;
        if (m.x) sc0 = -10000.0f;
        if (m.y) sc1 = -10000.0f;
        if (m.z) sc2 = -10000.0f;
        if (m.w) sc3 = -10000.0f;
        float e0 = exp_fast_s(sc0), e1 = exp_fast_s(sc1);
        float e2 = exp_fast_s(sc2), e3 = exp_fast_s(sc3);
        lsum += (e0 + e1) + (e2 + e3);
        prow[2 * q]     = __floats2half2_rn(e0, e1);
        prow[2 * q + 1] = __floats2half2_rn(e2, e3);
    }
    #pragma unroll
    for (int off = 16; off > 0; off >>= 1)
        lsum += __shfl_xor_sync(0xffffffffu, lsum, off);
    if (lane == 0) g_linv[rowg] = 1.0f / lsum;
}

// ---------------------------------------------------------------------------
// kB: pure fp16 GEMM  out = (P @ hT^T) * linv.
// Block 128 rows x 128 f, 8 warps (2m x 4n), warp tile 64x32, K(j)-tile 32.
// smem: A(P) 20480 | B(hT) 20480 | s_l 512   total 41472
// ---------------------------------------------------------------------------
#define KB_SMEM 41472

__global__ __launch_bounds__(256, 2)
void kB(float* __restrict__ out) {
    extern __shared__ unsigned char smraw[];
    __half* Ah  = (__half*)smraw;
    __half* Bh  = (__half*)(smraw + 20480);
    float*  s_l = (float*)(smraw + 40960);
    const uint32_t sb = smem_u32(smraw);

    const int tid = threadIdx.x;
    const int w = tid >> 5, lane = tid & 31;
    const int g = lane >> 2, tg = lane & 3;
    const int wm = w & 1, wn = w >> 1;
    const int i0 = blockIdx.x * 128;
    const int f0 = blockIdx.y * 128;
    const int b = blockIdx.z;
    const size_t rowg = (size_t)b * Nn + i0;

    if (tid < 128) s_l[tid] = g_linv[rowg + tid];

    float acc[4][4][4];
    #pragma unroll
    for (int mf = 0; mf < 4; mf++)
        #pragma unroll
        for (int nf = 0; nf < 4; nf++)
            #pragma unroll
            for (int q = 0; q < 4; q++) acc[mf][nf][q] = 0.0f;

    const __half* psrc0 = g_P + rowg * Nn;
    const __half* hsrc0 = g_hT + (size_t)b * Fn * Nn + (size_t)f0 * Nn;

    {
        #pragma unroll
        for (int q = 0; q < 2; q++) {
            int idx = tid + 256 * q, r = idx >> 2, ch = idx & 3;
            cp16(sb + (uint32_t)(r * SP + ch * 8) * 2,
                 psrc0 + (size_t)r * Nn + ch * 8);
        }
        #pragma unroll
        for (int q = 0; q < 2; q++) {
            int idx = tid + 256 * q, n = idx >> 2, ch = idx & 3;
            cp16(sb + 20480u + (uint32_t)(n * SP + ch * 8) * 2,
                 hsrc0 + (size_t)n * Nn + ch * 8);
        }
        CP_COMMIT();
    }

    #pragma unroll 1
    for (int c = 0; c < 64; c++) {
        const int buf = c & 1;
        CP_WAIT0();
        __syncthreads();

        if (c < 63) {
            const int nb = (c + 1) & 1;
            const __half* psrc = psrc0 + (c + 1) * 32;
            #pragma unroll
            for (int q = 0; q < 2; q++) {
                int idx = tid + 256 * q, r = idx >> 2, ch = idx & 3;
                cp16(sb + (uint32_t)(nb * 128 * SP + r * SP + ch * 8) * 2,
                     psrc + (size_t)r * Nn + ch * 8);
            }
            const __half* hsrc = hsrc0 + (c + 1) * 32;
            #pragma unroll
            for (int q = 0; q < 2; q++) {
                int idx = tid + 256 * q, n = idx >> 2, ch = idx & 3;
                cp16(sb + 20480u + (uint32_t)(nb * 128 * SP + n * SP + ch * 8) * 2,
                     hsrc + (size_t)n * Nn + ch * 8);
            }
            CP_COMMIT();
        }

        {
            const __half* A = Ah + buf * 128 * SP;
            const __half* B = Bh + buf * 128 * SP;
            #pragma unroll
            for (int ks = 0; ks < 2; ks++) {
                uint32_t bf[4][2];
                #pragma unroll
                for (int nf = 0; nf < 4; nf++) {
                    const __half* bp = B + (wn * 32 + nf * 8 + g) * SP + 16 * ks + 2 * tg;
                    bf[nf][0] = *(const uint32_t*)(bp);
                    bf[nf][1] = *(const uint32_t*)(bp + 8);
                }
                #pragma unroll
                for (int mf = 0; mf < 4; mf++) {
                    int rb = wm * 64 + mf * 16;
                    const __half* ap0 = A + (rb + g) * SP + 16 * ks + 2 * tg;
                    const __half* ap1 = A + (rb + g + 8) * SP + 16 * ks + 2 * tg;
                    uint32_t a0 = *(const uint32_t*)(ap0);
                    uint32_t a1 = *(const uint32_t*)(ap1);
                    uint32_t a2 = *(const uint32_t*)(ap0 + 8);
                    uint32_t a3 = *(const uint32_t*)(ap1 + 8);
                    #pragma unroll
                    for (int nf = 0; nf < 4; nf++)
                        mma16(acc[mf][nf], a0, a1, a2, a3, bf[nf][0], bf[nf][1]);
                }
            }
        }
        __syncthreads();
    }

    // epilogue: scale by 1/l, store fp32
    #pragma unroll
    for (int mf = 0; mf < 4; mf++) {
        int rl = wm * 64 + mf * 16 + g;
        float i0v = s_l[rl], i1v = s_l[rl + 8];
        size_t o0 = (rowg + rl) * Fn;
        size_t o1 = (rowg + rl + 8) * Fn;
        #pragma unroll
        for (int nf = 0; nf < 4; nf++) {
            int f = f0 + wn * 32 + nf * 8 + 2 * tg;
            float2 v0, v1;
            v0.x = acc[mf][nf][0] * i0v;
            v0.y = acc[mf][nf][1] * i0v;
            v1.x = acc[mf][nf][2] * i1v;
            v1.y = acc[mf][nf][3] * i1v;
            *(float2*)&out[o0 + f] = v0;
            *(float2*)&out[o1 + f] = v1;
        }
    }
}

// ---------------------------------------------------------------------------
extern "C" void kernel_launch(void* const* d_in, const int* in_sizes, int n_in,
                              void* d_out, int out_size) {
    const float* text  = (const float*)d_in[0];
    const int*   adj   = (const int*)  d_in[1];
    const float* W     = (const float*)d_in[2];
    const float* bias  = (const float*)d_in[3];
    const float* a_src = (const float*)d_in[4];
    const float* a_dst = (const float*)d_in[5];
    float* out = (float*)d_out;

    cudaFuncSetAttribute(kA, cudaFuncAttributeMaxDynamicSharedMemorySize, 40960);
    cudaFuncSetAttribute(kB, cudaFuncAttributeMaxDynamicSharedMemorySize, KB_SMEM);

    kW<<<dim3(16, 16), 256>>>(W);
    kA<<<dim3(128, 4), 256, 40960>>>(text, bias);
    kSD<<<dim3(Nn / 256, Bn, 4), 256>>>(a_src, a_dst);
    kSDr<<<64, 256>>>();
    kP<<<dim3(Nn / 8, Bn), 256>>>(adj);
    kB<<<dim3(16, 4, 8), 256, KB_SMEM>>>(out);
}

// round 8
// speedup vs baseline: 1.9885x; 1.1149x over previous
#include <cuda_runtime.h>
#include <cuda_fp16.h>
#include <cstdint>

#define Bn 8
#define Nn 2048
#define Fn 512

// ---------------------------------------------------------------------------
// Scratch (__device__ globals; no allocation allowed)
// ---------------------------------------------------------------------------
__device__ __half g_textH[Bn * Nn * Fn];      // text, half (16.8 MB)
__device__ __half g_hT[Bn * Fn * Nn];         // hidden^T [b][f][j], half (16.8 MB)
__device__ __half g_P[(size_t)Bn * Nn * Nn];  // P (scaled exp), half (67 MB)
__device__ __half g_Wh[Fn * Fn];              // W^T [f_out][f_in], half
__device__ float  g_s[Bn * Nn];
__device__ float  g_d[Bn * Nn];
__device__ float  g_sp[4][Bn * Nn];           // f-chunk partials
__device__ float  g_dp[4][Bn * Nn];
__device__ float  g_linv[Bn * Nn];

// ---------------------------------------------------------------------------
// Helpers
// ---------------------------------------------------------------------------
__device__ __forceinline__ uint32_t smem_u32(const void* p) {
    uint32_t a;
    asm("{ .reg .u64 t; cvta.to.shared.u64 t, %1; cvt.u32.u64 %0, t; }"
        : "=r"(a) : "l"(p));
    return a;
}
__device__ __forceinline__ void cp16(uint32_t dst, const void* src) {
    asm volatile("cp.async.cg.shared.global [%0], [%1], 16;"
                 :: "r"(dst), "l"(src));
}
#define CP_COMMIT() asm volatile("cp.async.commit_group;" ::: "memory")
#define CP_WAIT0()  asm volatile("cp.async.wait_group 0;" ::: "memory")

__device__ __forceinline__ void ldm4(uint32_t& r0, uint32_t& r1,
                                     uint32_t& r2, uint32_t& r3, uint32_t a) {
    asm volatile("ldmatrix.sync.aligned.m8n8.x4.shared.b16 {%0,%1,%2,%3}, [%4];"
                 : "=r"(r0), "=r"(r1), "=r"(r2), "=r"(r3) : "r"(a));
}

// fp16 m16n8k16, fp32 accumulate
__device__ __forceinline__ void mma16(float* c, uint32_t a0, uint32_t a1,
                                      uint32_t a2, uint32_t a3,
                                      uint32_t b0, uint32_t b1) {
    asm volatile("mma.sync.aligned.m16n8k16.row.col.f32.f16.f16.f32 "
        "{%0,%1,%2,%3},{%4,%5,%6,%7},{%8,%9},{%0,%1,%2,%3};"
        : "+f"(c[0]), "+f"(c[1]), "+f"(c[2]), "+f"(c[3])
        : "r"(a0), "r"(a1), "r"(a2), "r"(a3), "r"(b0), "r"(b1));
}

// exp(x) * 2^-4 via exp2 polynomial on FMA pipe.
__device__ __forceinline__ float exp_fast_s(float x) {
    float y = x * 1.4426950408889634f;
    y = fmaxf(y, -100.0f);
    float z = y + 12582912.0f;
    int   ei = __float_as_int(z) - 0x4B400000;
    float f = y - (z - 12582912.0f);
    float p = 1.3333558146e-3f;
    p = fmaf(p, f, 9.6181291076e-3f);
    p = fmaf(p, f, 5.5504108664e-2f);
    p = fmaf(p, f, 2.4022650695e-1f);
    p = fmaf(p, f, 6.9314718056e-1f);
    p = fmaf(p, f, 1.0f);
    return p * __int_as_float((ei + 123) << 23);   // 2^(ei-4)
}

// ---------------------------------------------------------------------------
// kTxt: convert text fp32 -> half (row-major unchanged)
// ---------------------------------------------------------------------------
__global__ __launch_bounds__(256)
void kTxt(const float* __restrict__ text) {
    int i = blockIdx.x * 256 + threadIdx.x;      // grid 4096 -> 1M uint4
    const float4* src = (const float4*)text;
    float4 v0 = src[2 * i], v1 = src[2 * i + 1];
    __half2 h0 = __floats2half2_rn(v0.x, v0.y);
    __half2 h1 = __floats2half2_rn(v0.z, v0.w);
    __half2 h2 = __floats2half2_rn(v1.x, v1.y);
    __half2 h3 = __floats2half2_rn(v1.z, v1.w);
    uint4 o;
    o.x = *(uint32_t*)&h0; o.y = *(uint32_t*)&h1;
    o.z = *(uint32_t*)&h2; o.w = *(uint32_t*)&h3;
    ((uint4*)g_textH)[i] = o;
}

// ---------------------------------------------------------------------------
// kW: g_Wh[n][k] = half(W[k][n])  (transpose + convert)
// ---------------------------------------------------------------------------
__global__ __launch_bounds__(256)
void kW(const float* __restrict__ W) {
    __shared__ float t[32][33];
    int tx = threadIdx.x & 31, ty = threadIdx.x >> 5;
    int bx = blockIdx.x, by = blockIdx.y;
    #pragma unroll
    for (int q = 0; q < 4; q++)
        t[ty + 8 * q][tx] = W[(by * 32 + ty + 8 * q) * Fn + bx * 32 + tx];
    __syncthreads();
    #pragma unroll
    for (int q = 0; q < 4; q++)
        g_Wh[(bx * 32 + ty + 8 * q) * Fn + by * 32 + tx] =
            __float2half_rn(t[tx][ty + 8 * q]);
}

// ---------------------------------------------------------------------------
// kA: hidden = textH @ WhT + b (fp16 mma, ldmatrix). Block 128 rows x 128 f,
// 8 warps (2m x 4n), warp tile 64x32, K-tile 32.
// Epilogue: smem transpose -> coalesced hT stores.
// smem: A 2*128*40*2=20480 | B 20480 ; epilogue reuses [0,34816) as 128x136 half
// ---------------------------------------------------------------------------
#define SP 40

__global__ __launch_bounds__(256, 2)
void kA(const float* __restrict__ bias) {
    extern __shared__ unsigned char smraw[];
    const uint32_t sb = smem_u32(smraw);

    const int tid = threadIdx.x;
    const int w = tid >> 5, lane = tid & 31;
    const int g = lane >> 2, tg = lane & 3;
    const int wm = w >> 2, wn = w & 3;
    const int row0 = blockIdx.x * 128;
    const int f0 = blockIdx.y * 128;
    const int bb = row0 >> 11;
    const int jbase = row0 & (Nn - 1);

    float acc[4][4][4];
    #pragma unroll
    for (int mf = 0; mf < 4; mf++)
        #pragma unroll
        for (int nf = 0; nf < 4; nf++)
            #pragma unroll
            for (int q = 0; q < 4; q++) acc[mf][nf][q] = 0.0f;

    const __half* asrc0 = g_textH + (size_t)row0 * Fn;
    const __half* bsrc0 = g_Wh + (size_t)f0 * Fn;

    // issue tile 0
    {
        #pragma unroll
        for (int q = 0; q < 2; q++) {
            int idx = tid + 256 * q, r = idx >> 2, ch = idx & 3;
            cp16(sb + (uint32_t)(r * SP + ch * 8) * 2,
                 asrc0 + (size_t)r * Fn + ch * 8);
        }
        #pragma unroll
        for (int q = 0; q < 2; q++) {
            int idx = tid + 256 * q, n = idx >> 2, ch = idx & 3;
            cp16(sb + 20480u + (uint32_t)(n * SP + ch * 8) * 2,
                 bsrc0 + (size_t)n * Fn + ch * 8);
        }
        CP_COMMIT();
    }

    // ldmatrix lane address offsets (in halves)
    const int arow_off = wm * 64 + (lane & 15);          // + mf*16
    const int akc_off  = (lane >> 4) << 3;               // + 16*ks
    const int brow01   = wn * 32 + ((lane >> 4) << 3) + (lane & 7);  // nf 0/1
    const int bkc_off  = ((lane >> 3) & 1) << 3;         // + 16*ks

    #pragma unroll 1
    for (int c = 0; c < 16; c++) {
        const int buf = c & 1;
        CP_WAIT0();
        __syncthreads();

        if (c < 15) {
            const int nb = (c + 1) & 1;
            const __half* asrc = asrc0 + (c + 1) * 32;
            #pragma unroll
            for (int q = 0; q < 2; q++) {
                int idx = tid + 256 * q, r = idx >> 2, ch = idx & 3;
                cp16(sb + (uint32_t)(nb * 128 * SP + r * SP + ch * 8) * 2,
                     asrc + (size_t)r * Fn + ch * 8);
            }
            const __half* bsrc = bsrc0 + (c + 1) * 32;
            #pragma unroll
            for (int q = 0; q < 2; q++) {
                int idx = tid + 256 * q, n = idx >> 2, ch = idx & 3;
                cp16(sb + 20480u + (uint32_t)(nb * 128 * SP + n * SP + ch * 8) * 2,
                     bsrc + (size_t)n * Fn + ch * 8);
            }
            CP_COMMIT();
        }

        const uint32_t Ab = sb + (uint32_t)(buf * 128 * SP) * 2;
        const uint32_t Bb = sb + 20480u + (uint32_t)(buf * 128 * SP) * 2;
        #pragma unroll
        for (int ks = 0; ks < 2; ks++) {
            uint32_t af[4][4], bf[4][2];
            #pragma unroll
            for (int mf = 0; mf < 4; mf++)
                ldm4(af[mf][0], af[mf][1], af[mf][2], af[mf][3],
                     Ab + (uint32_t)((arow_off + mf * 16) * SP + 16 * ks + akc_off) * 2);
            ldm4(bf[0][0], bf[0][1], bf[1][0], bf[1][1],
                 Bb + (uint32_t)(brow01 * SP + 16 * ks + bkc_off) * 2);
            ldm4(bf[2][0], bf[2][1], bf[3][0], bf[3][1],
                 Bb + (uint32_t)((brow01 + 16) * SP + 16 * ks + bkc_off) * 2);
            #pragma unroll
            for (int mf = 0; mf < 4; mf++)
                #pragma unroll
                for (int nf = 0; nf < 4; nf++)
                    mma16(acc[mf][nf], af[mf][0], af[mf][1], af[mf][2], af[mf][3],
                          bf[nf][0], bf[nf][1]);
        }
    }

    // epilogue: acc -> smem transpose tile [f][j] (128x136 halves), then
    // coalesced uint4 stores into g_hT.
    __syncthreads();
    __half* T = (__half*)smraw;
    #pragma unroll
    for (int mf = 0; mf < 4; mf++) {
        int jl = wm * 64 + mf * 16 + g;
        #pragma unroll
        for (int nf = 0; nf < 4; nf++) {
            int fl = wn * 32 + nf * 8 + 2 * tg;
            float b0v = __ldg(bias + f0 + fl), b1v = __ldg(bias + f0 + fl + 1);
            T[fl * 136 + jl]           = __float2half_rn(acc[mf][nf][0] + b0v);
            T[(fl + 1) * 136 + jl]     = __float2half_rn(acc[mf][nf][1] + b1v);
            T[fl * 136 + jl + 8]       = __float2half_rn(acc[mf][nf][2] + b0v);
            T[(fl + 1) * 136 + jl + 8] = __float2half_rn(acc[mf][nf][3] + b1v);
        }
    }
    __syncthreads();
    __half* hb = g_hT + (size_t)bb * Fn * Nn + jbase;
    #pragma unroll
    for (int q = 0; q < 8; q++) {
        int idx = q * 256 + tid;
        int fr = idx >> 4, jc = idx & 15;
        uint4 v = *(uint4*)&T[fr * 136 + jc * 8];
        *(uint4*)(hb + (size_t)(f0 + fr) * Nn + jc * 8) = v;
    }
}

// ---------------------------------------------------------------------------
// kSD stage 1: partial dot products over a 128-f chunk.
// ---------------------------------------------------------------------------
__global__ __launch_bounds__(256)
void kSD(const float* __restrict__ a_src, const float* __restrict__ a_dst) {
    __shared__ float sa[128], sd[128];
    const int tid = threadIdx.x;
    const int j = blockIdx.x * 256 + tid;
    const int b = blockIdx.y;
    const int fc = blockIdx.z;
    if (tid < 128) { sa[tid] = a_src[fc * 128 + tid]; sd[tid] = a_dst[fc * 128 + tid]; }
    __syncthreads();
    const __half* h = g_hT + (size_t)b * Fn * Nn + (size_t)fc * 128 * Nn + j;
    float ss = 0.0f, dd = 0.0f;
    #pragma unroll 16
    for (int f = 0; f < 128; f++) {
        float v = __half2float(h[(size_t)f * Nn]);
        ss = fmaf(v, sa[f], ss);
        dd = fmaf(v, sd[f], dd);
    }
    g_sp[fc][b * Nn + j] = ss;
    g_dp[fc][b * Nn + j] = dd;
}

__global__ __launch_bounds__(256)
void kSDr() {
    const int i = blockIdx.x * 256 + threadIdx.x;
    g_s[i] = (g_sp[0][i] + g_sp[1][i]) + (g_sp[2][i] + g_sp[3][i]);
    g_d[i] = (g_dp[0][i] + g_dp[1][i]) + (g_dp[2][i] + g_dp[3][i]);
}

// ---------------------------------------------------------------------------
// kP: warp-per-row P + 1/rowsum.
// ---------------------------------------------------------------------------
__global__ __launch_bounds__(256)
void kP(const int* __restrict__ adj) {
    const int tid = threadIdx.x, w = tid >> 5, lane = tid & 31;
    const int b = blockIdx.y;
    const int r = blockIdx.x * 8 + w;
    const size_t rowg = (size_t)b * Nn + r;
    const float si = g_s[rowg];
    const int4*   arow = (const int4*)(adj + rowg * Nn);
    const float4* dsrc = (const float4*)(g_d + (size_t)b * Nn);
    __half2* prow = (__half2*)(g_P + rowg * Nn);

    float lsum = 0.0f;
    #pragma unroll
    for (int q0 = 0; q0 < 16; q0++) {
        const int q = q0 * 32 + lane;
        int4 m = __ldg(arow + q);
        float4 dv = __ldg(dsrc + q);
        float sc0 = si + dv.x, sc1 = si + dv.y;
        float sc2 = si + dv.z, sc3 = si + dv.w;
        sc0 = (sc0 >= 0.0f) ? sc0 : 0.2f * sc0;
        sc1 = (sc1 >= 0.0f) ? sc1 : 0.2f * sc1;
        sc2 = (sc2 >= 0.0f) ? sc2 : 0.2f * sc2;
        sc3 = (sc3 >= 0.0f) ? sc3 : 0.2f * sc3;
        if (m.x) sc0 = -10000.0f;
        if (m.y) sc1 = -10000.0f;
        if (m.z) sc2 = -10000.0f;
        if (m.w) sc3 = -10000.0f;
        float e0 = exp_fast_s(sc0), e1 = exp_fast_s(sc1);
        float e2 = exp_fast_s(sc2), e3 = exp_fast_s(sc3);
        lsum += (e0 + e1) + (e2 + e3);
        prow[2 * q]     = __floats2half2_rn(e0, e1);
        prow[2 * q + 1] = __floats2half2_rn(e2, e3);
    }
    #pragma unroll
    for (int off = 16; off > 0; off >>= 1)
        lsum += __shfl_xor_sync(0xffffffffu, lsum, off);
    if (lane == 0) g_linv[rowg] = 1.0f / lsum;
}

// ---------------------------------------------------------------------------
// kB: pure fp16 GEMM out = (P @ hT^T) * linv (ldmatrix, 1 sync/ktile).
// Block 128 rows x 128 f, 8 warps (2m x 4n), warp tile 64x32, K(j)-tile 32.
// smem: A(P) 20480 | B(hT) 20480 | s_l 512  total 41472
// ---------------------------------------------------------------------------
#define KB_SMEM 41472

__global__ __launch_bounds__(256, 2)
void kB(float* __restrict__ out) {
    extern __shared__ unsigned char smraw[];
    float*  s_l = (float*)(smraw + 40960);
    const uint32_t sb = smem_u32(smraw);

    const int tid = threadIdx.x;
    const int w = tid >> 5, lane = tid & 31;
    const int g = lane >> 2, tg = lane & 3;
    const int wm = w & 1, wn = w >> 1;
    const int i0 = blockIdx.x * 128;
    const int f0 = blockIdx.y * 128;
    const int b = blockIdx.z;
    const size_t rowg = (size_t)b * Nn + i0;

    if (tid < 128) s_l[tid] = g_linv[rowg + tid];

    float acc[4][4][4];
    #pragma unroll
    for (int mf = 0; mf < 4; mf++)
        #pragma unroll
        for (int nf = 0; nf < 4; nf++)
            #pragma unroll
            for (int q = 0; q < 4; q++) acc[mf][nf][q] = 0.0f;

    const __half* psrc0 = g_P + rowg * Nn;
    const __half* hsrc0 = g_hT + (size_t)b * Fn * Nn + (size_t)f0 * Nn;

    {
        #pragma unroll
        for (int q = 0; q < 2; q++) {
            int idx = tid + 256 * q, r = idx >> 2, ch = idx & 3;
            cp16(sb + (uint32_t)(r * SP + ch * 8) * 2,
                 psrc0 + (size_t)r * Nn + ch * 8);
        }
        #pragma unroll
        for (int q = 0; q < 2; q++) {
            int idx = tid + 256 * q, n = idx >> 2, ch = idx & 3;
            cp16(sb + 20480u + (uint32_t)(n * SP + ch * 8) * 2,
                 hsrc0 + (size_t)n * Nn + ch * 8);
        }
        CP_COMMIT();
    }

    const int arow_off = wm * 64 + (lane & 15);
    const int akc_off  = (lane >> 4) << 3;
    const int brow01   = wn * 32 + ((lane >> 4) << 3) + (lane & 7);
    const int bkc_off  = ((lane >> 3) & 1) << 3;

    #pragma unroll 1
    for (int c = 0; c < 64; c++) {
        const int buf = c & 1;
        CP_WAIT0();
        __syncthreads();

        if (c < 63) {
            const int nb = (c + 1) & 1;
            const __half* psrc = psrc0 + (c + 1) * 32;
            #pragma unroll
            for (int q = 0; q < 2; q++) {
                int idx = tid + 256 * q, r = idx >> 2, ch = idx & 3;
                cp16(sb + (uint32_t)(nb * 128 * SP + r * SP + ch * 8) * 2,
                     psrc + (size_t)r * Nn + ch * 8);
            }
            const __half* hsrc = hsrc0 + (c + 1) * 32;
            #pragma unroll
            for (int q = 0; q < 2; q++) {
                int idx = tid + 256 * q, n = idx >> 2, ch = idx & 3;
                cp16(sb + 20480u + (uint32_t)(nb * 128 * SP + n * SP + ch * 8) * 2,
                     hsrc + (size_t)n * Nn + ch * 8);
            }
            CP_COMMIT();
        }

        const uint32_t Ab = sb + (uint32_t)(buf * 128 * SP) * 2;
        const uint32_t Bb = sb + 20480u + (uint32_t)(buf * 128 * SP) * 2;
        #pragma unroll
        for (int ks = 0; ks < 2; ks++) {
            uint32_t af[4][4], bf[4][2];
            #pragma unroll
            for (int mf = 0; mf < 4; mf++)
                ldm4(af[mf][0], af[mf][1], af[mf][2], af[mf][3],
                     Ab + (uint32_t)((arow_off + mf * 16) * SP + 16 * ks + akc_off) * 2);
            ldm4(bf[0][0], bf[0][1], bf[1][0], bf[1][1],
                 Bb + (uint32_t)(brow01 * SP + 16 * ks + bkc_off) * 2);
            ldm4(bf[2][0], bf[2][1], bf[3][0], bf[3][1],
                 Bb + (uint32_t)((brow01 + 16) * SP + 16 * ks + bkc_off) * 2);
            #pragma unroll
            for (int mf = 0; mf < 4; mf++)
                #pragma unroll
                for (int nf = 0; nf < 4; nf++)
                    mma16(acc[mf][nf], af[mf][0], af[mf][1], af[mf][2], af[mf][3],
                          bf[nf][0], bf[nf][1]);
        }
    }

    // epilogue: scale by 1/l, store fp32
    #pragma unroll
    for (int mf = 0; mf < 4; mf++) {
        int rl = wm * 64 + mf * 16 + g;
        float i0v = s_l[rl], i1v = s_l[rl + 8];
        size_t o0 = (rowg + rl) * Fn;
        size_t o1 = (rowg + rl + 8) * Fn;
        #pragma unroll
        for (int nf = 0; nf < 4; nf++) {
            int f = f0 + wn * 32 + nf * 8 + 2 * tg;
            float2 v0, v1;
            v0.x = acc[mf][nf][0] * i0v;
            v0.y = acc[mf][nf][1] * i0v;
            v1.x = acc[mf][nf][2] * i1v;
            v1.y = acc[mf][nf][3] * i1v;
            *(float2*)&out[o0 + f] = v0;
            *(float2*)&out[o1 + f] = v1;
        }
    }
}

// ---------------------------------------------------------------------------
extern "C" void kernel_launch(void* const* d_in, const int* in_sizes, int n_in,
                              void* d_out, int out_size) {
    const float* text  = (const float*)d_in[0];
    const int*   adj   = (const int*)  d_in[1];
    const float* W     = (const float*)d_in[2];
    const float* bias  = (const float*)d_in[3];
    const float* a_src = (const float*)d_in[4];
    const float* a_dst = (const float*)d_in[5];
    float* out = (float*)d_out;

    cudaFuncSetAttribute(kA, cudaFuncAttributeMaxDynamicSharedMemorySize, 40960);
    cudaFuncSetAttribute(kB, cudaFuncAttributeMaxDynamicSharedMemorySize, KB_SMEM);

    kTxt<<<4096, 256>>>(text);
    kW<<<dim3(16, 16), 256>>>(W);
    kA<<<dim3(128, 4), 256, 40960>>>(bias);
    kSD<<<dim3(Nn / 256, Bn, 4), 256>>>(a_src, a_dst);
    kSDr<<<64, 256>>>();
    kP<<<dim3(Nn / 8, Bn), 256>>>(adj);
    kB<<<dim3(16, 4, 8), 256, KB_SMEM>>>(out);
}